// round 6
// baseline (speedup 1.0000x reference)
#include <cuda_runtime.h>
#include <math.h>
#include <stdint.h>

#define NB 64
#define NP 8732
#define NO 12
#define NC 81
#define ROWW 85
#define JT 0.5f

// -------- scratch (device globals) --------
__device__ float g_ce_pos;
__device__ float g_ce_topk;
__device__ float g_ll[NB];
__device__ int   g_numpos[NB];
__device__ unsigned char g_conf[NB * NP];
__device__ float g_ceneg[NB * NP];

__device__ __forceinline__ float sl1(float d) {
    float ad = fabsf(d);
    return ad < 1.f ? 0.5f * d * d : ad - 0.5f;
}

__device__ __forceinline__ float iou_fast(float4 t, float ta,
                                          float px0, float py0, float px1, float py1,
                                          float pa) {
    float ix = fmaxf(fminf(t.z, px1) - fmaxf(t.x, px0), 0.f);
    float iy = fmaxf(fminf(t.w, py1) - fmaxf(t.y, py0), 0.f);
    float inter = ix * iy;
    return __fdividef(inter, ta + pa - inter);
}

// ---------------- fused match: both passes, one block per batch ----------------
__global__ void __launch_bounds__(256) match_kernel(
    const float* __restrict__ pred,
    const float* __restrict__ truths,   // (B, O, 4) point form
    const int*   __restrict__ labels,   // (B, O)
    const float* __restrict__ dbox)     // (P, 4) center form
{
    const int b = blockIdx.x;
    const int tid = threadIdx.x;

    __shared__ float4 s_t[NO];
    __shared__ float  s_area[NO];
    __shared__ int    s_lab[NO];
    __shared__ unsigned long long s_best[NO];
    __shared__ int    s_bp[NO];
    __shared__ float  s_ll;
    __shared__ int    s_np;

    if (tid < NO) {
        float4 t = ((const float4*)truths)[b * NO + tid];
        s_t[tid] = t;
        s_area[tid] = (t.z - t.x) * (t.w - t.y);
        s_lab[tid] = labels[b * NO + tid];
        s_best[tid] = 0ull;
    }
    if (tid == 0) {
        s_ll = 0.f; s_np = 0;
        if (b == 0) { g_ce_pos = 0.f; g_ce_topk = 0.f; }  // before ce in stream
    }
    __syncthreads();

    // ---- pass 1: per-truth best prior (first-occurrence ties via ~p) ----
    unsigned long long lb[NO];
#pragma unroll
    for (int o = 0; o < NO; ++o) lb[o] = 0ull;

    const float4* db = (const float4*)dbox;
    for (int p = tid; p < NP; p += 256) {
        float4 d = db[p];
        float px0 = d.x - 0.5f * d.z, py0 = d.y - 0.5f * d.w;
        float px1 = d.x + 0.5f * d.z, py1 = d.y + 0.5f * d.w;
        float pa = d.z * d.w;
#pragma unroll
        for (int o = 0; o < NO; ++o) {
            float iou = iou_fast(s_t[o], s_area[o], px0, py0, px1, py1, pa);
            unsigned long long key =
                ((unsigned long long)__float_as_uint(iou) << 32) | (unsigned)(~p);
            lb[o] = (key > lb[o]) ? key : lb[o];
        }
    }
    // warp-reduce each truth's key, then one atomic per warp per truth
#pragma unroll
    for (int o = 0; o < NO; ++o) {
#pragma unroll
        for (int off = 16; off; off >>= 1) {
            unsigned long long other = __shfl_xor_sync(0xffffffffu, lb[o], off);
            lb[o] = (other > lb[o]) ? other : lb[o];
        }
    }
    if ((tid & 31) == 0) {
#pragma unroll
        for (int o = 0; o < NO; ++o) atomicMax(&s_best[o], lb[o]);
    }
    __syncthreads();
    if (tid < NO) s_bp[tid] = (int)(~(unsigned)(s_best[tid] & 0xFFFFFFFFull));
    __syncthreads();

    // ---- pass 2: per-prior best truth, override, conf_t, loc loss ----
    float ll = 0.f;
    int np = 0;
    for (int p = tid; p < NP; p += 256) {
        float4 d = db[p];
        float px0 = d.x - 0.5f * d.z, py0 = d.y - 0.5f * d.w;
        float px1 = d.x + 0.5f * d.z, py1 = d.y + 0.5f * d.w;
        float pa = d.z * d.w;
        float bov = -1.f;
        int bi = 0;
#pragma unroll
        for (int o = 0; o < NO; ++o) {
            float iou = iou_fast(s_t[o], s_area[o], px0, py0, px1, py1, pa);
            if (iou > bov) { bov = iou; bi = o; }   // first max wins
        }
#pragma unroll
        for (int o = 0; o < NO; ++o)
            if (s_bp[o] == p) { bov = 2.f; bi = o; }   // last write wins

        int conf = (bov < JT) ? 0 : (s_lab[bi] + 1);
        g_conf[b * NP + p] = (unsigned char)conf;

        if (conf > 0) {
            np++;
            float4 t = s_t[bi];
            float gx = ((t.x + t.z) * 0.5f - d.x) * __fdividef(10.f, d.z);
            float gy = ((t.y + t.w) * 0.5f - d.y) * __fdividef(10.f, d.w);
            float gw = __logf(__fdividef(t.z - t.x, d.z)) * 5.0f;
            float gh = __logf(__fdividef(t.w - t.y, d.w)) * 5.0f;
            const float* lp = pred + ((size_t)b * NP + p) * ROWW;
            ll += sl1(lp[0] - gx) + sl1(lp[1] - gy) +
                  sl1(lp[2] - gw) + sl1(lp[3] - gh);
        }
    }
#pragma unroll
    for (int off = 16; off; off >>= 1) {
        ll += __shfl_xor_sync(0xffffffffu, ll, off);
        np += __shfl_xor_sync(0xffffffffu, np, off);
    }
    if ((tid & 31) == 0) { atomicAdd(&s_ll, ll); atomicAdd(&s_np, np); }
    __syncthreads();
    if (tid == 0) { g_ll[b] = s_ll; g_numpos[b] = s_np; }
}

// ---------------- CE: 8 lanes per prior, fast exp/log ----------------
__global__ void __launch_bounds__(256) ce_kernel(const float* __restrict__ pred) {
    const int warp = (int)((blockIdx.x * 256u + threadIdx.x) >> 5);
    const int lane = threadIdx.x & 31;
    const int sub = lane & 7;                 // position within 8-lane group
    const int pr = warp * 4 + (lane >> 3);    // prior handled by this group

    const int t = (int)g_conf[pr];            // independent chain, issue early
    const float* row = pred + (size_t)pr * ROWW + 4;
    const float xt = __ldg(row + t);          // tgt logit (conf in [0,80])

    float x[11];
    float m = -INFINITY;
#pragma unroll
    for (int j = 0; j < 10; ++j) {            // indices 0..79: always valid
        x[j] = __ldg(row + j * 8 + sub);
        m = fmaxf(m, x[j]);
    }
    x[10] = (sub == 0) ? __ldg(row + 80) : -INFINITY;
    m = fmaxf(m, x[10]);

    m = fmaxf(m, __shfl_xor_sync(0xffffffffu, m, 4));
    m = fmaxf(m, __shfl_xor_sync(0xffffffffu, m, 2));
    m = fmaxf(m, __shfl_xor_sync(0xffffffffu, m, 1));

    float e = 0.f;
#pragma unroll
    for (int j = 0; j < 11; ++j)
        e += __expf(x[j] - m);                // exp(-inf) -> 0
    e += __shfl_xor_sync(0xffffffffu, e, 4);
    e += __shfl_xor_sync(0xffffffffu, e, 2);
    e += __shfl_xor_sync(0xffffffffu, e, 1);

    if (sub == 0) {
        float ce = m + __logf(e) - xt;
        if (t > 0) {
            atomicAdd(&g_ce_pos, ce);
            g_ceneg[pr] = 0.f;
        } else {
            g_ceneg[pr] = ce;
        }
    }
}

// ---------------- per-batch top-k sum: MSD radix-256, match-aggregated ----------------
__global__ void __launch_bounds__(1024) topk_kernel() {
    const int b = blockIdx.x;
    const int tid = threadIdx.x;

    __shared__ unsigned keys[NP];             // ~35 KB
    __shared__ int  hist[257];
    __shared__ unsigned s_v;
    __shared__ int  s_k;
    __shared__ int  s_cnt;
    __shared__ float s_sum;

    for (int i = tid; i < NP; i += 1024)
        keys[i] = __float_as_uint(g_ceneg[b * NP + i]);   // all >= 0
    int k0 = g_numpos[b] * 3;
    if (k0 > NP) k0 = NP;
    __syncthreads();
    if (k0 <= 0) return;

    unsigned v = 0;
    int kk = k0;
    for (int shift = 24; shift >= 0; shift -= 8) {
        if (tid < 256) hist[tid] = 0;
        if (tid == 0) hist[256] = 0;
        __syncthreads();
        const unsigned prefmask = (shift == 24) ? 0u : (0xFFFFFFFFu << (shift + 8));
        for (int base = 0; base < NP; base += 1024) {
            int i = base + tid;
            unsigned kv = (i < NP) ? keys[i] : 0u;
            bool pred = (i < NP) && ((kv & prefmask) == v);
            unsigned ballot = __ballot_sync(0xffffffffu, pred);
            if (pred) {
                int bin = (int)((kv >> shift) & 255u);
                unsigned peers = __match_any_sync(ballot, bin);
                int leader = __ffs(peers) - 1;
                if ((tid & 31) == leader)
                    atomicAdd(&hist[bin], (int)__popc(peers));
            }
        }
        __syncthreads();
        // suffix sum over 256 bins (Hillis-Steele), all threads hit barriers
        for (int d = 1; d < 256; d <<= 1) {
            int val = 0;
            if (tid < 256) {
                val = hist[tid];
                if (tid + d < 256) val += hist[tid + d];
            }
            __syncthreads();
            if (tid < 256) hist[tid] = val;
            __syncthreads();
        }
        // pick bin: suffix[bb+1] < kk <= suffix[bb]
        if (tid < 256) {
            int above = (tid == 255) ? 0 : hist[tid + 1];
            if (hist[tid] >= kk && above < kk) {
                s_v = v | ((unsigned)tid << shift);
                s_k = kk - above;
            }
        }
        __syncthreads();
        v = s_v; kk = s_k;
        __syncthreads();
    }

    // v = exact k-th largest key; sum strictly-greater + tie correction
    int cgt = 0;
    float sgt = 0.f;
    for (int i = tid; i < NP; i += 1024) {
        unsigned kv = keys[i];
        if (kv > v) { cgt++; sgt += __uint_as_float(kv); }
    }
#pragma unroll
    for (int off = 16; off; off >>= 1) {
        cgt += __shfl_xor_sync(0xffffffffu, cgt, off);
        sgt += __shfl_xor_sync(0xffffffffu, sgt, off);
    }
    if (tid == 0) { s_cnt = 0; s_sum = 0.f; }
    __syncthreads();
    if ((tid & 31) == 0) { atomicAdd(&s_cnt, cgt); atomicAdd(&s_sum, sgt); }
    __syncthreads();
    if (tid == 0) {
        float total = s_sum + (float)(k0 - s_cnt) * __uint_as_float(v);
        atomicAdd(&g_ce_topk, total);
    }
}

// ---------------- finalize ----------------
__global__ void finalize_kernel(float* __restrict__ out) {
    int N = 0;
    float ll = 0.f;
    for (int b = 0; b < NB; ++b) { N += g_numpos[b]; ll += g_ll[b]; }
    float fN = (float)N;
    out[0] = ll / fN;
    out[1] = (g_ce_pos + g_ce_topk) / fN;
}

extern "C" void kernel_launch(void* const* d_in, const int* in_sizes, int n_in,
                              void* d_out, int out_size) {
    const float* pred   = (const float*)d_in[0];
    const float* truths = (const float*)d_in[1];
    const int*   labels = (const int*)d_in[2];
    const float* dbox   = (const float*)d_in[3];
    float* out = (float*)d_out;

    match_kernel<<<NB, 256>>>(pred, truths, labels, dbox);

    // NB*NP = 558848 priors, 4 priors/warp, 8 warps/block -> 17464 blocks
    const int ce_blocks = (NB * NP) / 32;
    ce_kernel<<<ce_blocks, 256>>>(pred);

    topk_kernel<<<NB, 1024>>>();
    finalize_kernel<<<1, 1>>>(out);
}